// round 8
// baseline (speedup 1.0000x reference)
#include <cuda_runtime.h>
#include <cstdint>

// Problem constants
#define B_ 8
#define T_ 64
#define N_ 512
#define D_ 64
#define KH_ 8
#define NEG_ (-32767.0f)

// smem (floats), per problem (EXACT round-5 layout):
//   H  : 64 x 132 (concat(x,ste); cols 64..127 reused as score buf S0; cols 0..63 as attn out O)
//   Qf : 64 x 68  (q; reused as FFN hidden U)
//   Kf : 64 x 68
//   Vf : 64 x 68
//   S1 : 64 x 68  (second score buffer)
#define H_STR   132
#define QKV_STR 68
#define S1_STR  68
#define PROB_SZ (64 * H_STR + 4 * 64 * QKV_STR)   // 25856 floats
#define SMEM_FLOATS (2 * PROB_SZ)                 // 51712 floats = 206848 B

// Pre-split weights, per-matrix layout identical to the fp32 originals: [k*64 + n]
__device__ __align__(16) float2 g_wqs[128 * 64];
__device__ __align__(16) float2 g_wks[128 * 64];
__device__ __align__(16) float2 g_wvs[128 * 64];
__device__ __align__(16) float2 g_w1s[64 * 64];
__device__ __align__(16) float2 g_w2s[64 * 64];

// ---- tf32 helpers ----
__device__ __forceinline__ uint32_t tf32_hi(float v) {
    uint32_t h;
    asm("cvt.rna.tf32.f32 %0, %1;" : "=r"(h) : "f"(v));
    return h;
}
__device__ __forceinline__ void tf32_split(float v, uint32_t& hi, uint32_t& lo) {
    hi = tf32_hi(v);
    float l = v - __uint_as_float(hi);
    lo = tf32_hi(l);
}
__device__ __forceinline__ float2 split2(float v) {
    uint32_t h = tf32_hi(v);
    float l = v - __uint_as_float(h);
    return make_float2(__uint_as_float(h), __uint_as_float(tf32_hi(l)));
}
__device__ __forceinline__ void mma8(float c[4], const uint32_t a[4], const uint32_t b[2]) {
    asm volatile(
        "mma.sync.aligned.m16n8k8.row.col.f32.tf32.tf32.f32 "
        "{%0,%1,%2,%3}, {%4,%5,%6,%7}, {%8,%9}, {%0,%1,%2,%3};"
        : "+f"(c[0]), "+f"(c[1]), "+f"(c[2]), "+f"(c[3])
        : "r"(a[0]), "r"(a[1]), "r"(a[2]), "r"(a[3]), "r"(b[0]), "r"(b[1]));
}

// ---- setup kernel: pre-split all weights ----
__global__ void prep_weights(const float* __restrict__ Wq, const float* __restrict__ Wk,
                             const float* __restrict__ Wv, const float* __restrict__ W1,
                             const float* __restrict__ W2)
{
    int idx = blockIdx.x * 256 + threadIdx.x;
    if (idx < 8192)       g_wqs[idx] = split2(Wq[idx]);
    else if (idx < 16384) g_wks[idx - 8192]  = split2(Wk[idx - 8192]);
    else if (idx < 24576) g_wvs[idx - 16384] = split2(Wv[idx - 16384]);
    else if (idx < 28672) g_w1s[idx - 24576] = split2(W1[idx - 24576]);
    else if (idx < 32768) g_w2s[idx - 28672] = split2(W2[idx - 28672]);
}

// 64xN-slab GEMM accumulate (round-5 structure, pre-split B):
// acc[4][4] covers rows mtile*16..+16, cols nhalf*32..+32
// B element (k, n) read at Wp[k*64 + n] exactly where round 5 read W[k*64 + n].
template<int KSTEPS, int ASTR>
__device__ __forceinline__ void mma_gemm64(const float* __restrict__ A,
                                           const float2* __restrict__ Wp,
                                           float acc[4][4],
                                           int mtile, int nhalf, int g, int tq)
{
    const float* Ab = A + mtile * 16 * ASTR;
    #pragma unroll
    for (int kk = 0; kk < KSTEPS; kk++) {
        const int k0 = kk * 8;
        uint32_t ah[4], al[4];
        tf32_split(Ab[g * ASTR + k0 + tq],           ah[0], al[0]);
        tf32_split(Ab[(g + 8) * ASTR + k0 + tq],     ah[1], al[1]);
        tf32_split(Ab[g * ASTR + k0 + tq + 4],       ah[2], al[2]);
        tf32_split(Ab[(g + 8) * ASTR + k0 + tq + 4], ah[3], al[3]);

        #pragma unroll
        for (int nt = 0; nt < 4; nt++) {
            const int nb = nhalf * 32 + nt * 8 + g;
            float2 b0 = Wp[(k0 + tq) * 64 + nb];
            float2 b1 = Wp[(k0 + tq + 4) * 64 + nb];
            uint32_t bh[2] = {__float_as_uint(b0.x), __float_as_uint(b1.x)};
            uint32_t bl[2] = {__float_as_uint(b0.y), __float_as_uint(b1.y)};
            mma8(acc[nt], ah, bh);
            mma8(acc[nt], ah, bl);
            mma8(acc[nt], al, bh);
        }
    }
}

// softmax of one 64-wide row with 4 cooperating lanes (round-5 scalar version)
__device__ __forceinline__ void softmax_row(float* __restrict__ row, int l4) {
    float v[16];
    float mx = -1e30f;
    #pragma unroll
    for (int k = 0; k < 16; k++) { v[k] = row[l4 + 4 * k]; mx = fmaxf(mx, v[k]); }
    mx = fmaxf(mx, __shfl_xor_sync(0xffffffffu, mx, 1));
    mx = fmaxf(mx, __shfl_xor_sync(0xffffffffu, mx, 2));
    float sum = 0.0f;
    #pragma unroll
    for (int k = 0; k < 16; k++) { v[k] = __expf(v[k] - mx); sum += v[k]; }
    sum += __shfl_xor_sync(0xffffffffu, sum, 1);
    sum += __shfl_xor_sync(0xffffffffu, sum, 2);
    float inv = 1.0f / sum;
    #pragma unroll
    for (int k = 0; k < 16; k++) row[l4 + 4 * k] = v[k] * inv;
}

__global__ __launch_bounds__(512, 1)
void temporal_attn_kernel(
    const float* __restrict__ x,  const float* __restrict__ ste,
    const float* __restrict__ bq, const float* __restrict__ bk,
    const float* __restrict__ bv, const float* __restrict__ b1,
    const float* __restrict__ b2, float* __restrict__ out)
{
    extern __shared__ float sm[];
    const int tid  = threadIdx.x;
    const int pid  = tid >> 8;           // which of 2 problems
    const int ltid = tid & 255;

    const int p = blockIdx.x * 2 + pid;
    const int n = p & (N_ - 1);
    const int b = p >> 9;

    float* H  = sm + pid * PROB_SZ;
    float* Qf = H  + 64 * H_STR;
    float* Kf = Qf + 64 * QKV_STR;
    float* Vf = Kf + 64 * QKV_STR;
    float* S1 = Vf + 64 * QKV_STR;
    float* S0 = H + 64;                  // score buf 0: H cols 64..127 (stride 132)

    // ---- load H = concat(x, ste): 64 x 128, float4 ----
    {
        const float* xb = x   + ((size_t)((size_t)b * T_) * N_ + n) * D_;
        const float* sb = ste + ((size_t)((size_t)b * T_) * N_ + n) * D_;
        #pragma unroll
        for (int i = 0; i < 4; i++) {
            int idx = ltid + i * 256;
            int t = idx >> 4, f4 = (idx & 15) << 2;
            size_t g = (size_t)t * (N_ * D_) + f4;
            *(float4*)&H[t * H_STR + f4]      = *(const float4*)&xb[g];
            *(float4*)&H[t * H_STR + 64 + f4] = *(const float4*)&sb[g];
        }
    }
    __syncthreads();

    // warp/lane mapping
    const int lane  = tid & 31;
    const int wl    = (tid >> 5) & 7;
    const int g     = lane >> 2;
    const int tq    = lane & 3;
    const int mtile = wl & 3;
    const int nhalf = wl >> 2;
    const int hsel  = wl >> 2;

    // ---- QKV projections (3 passes, pre-split weights) ----
    #pragma unroll 1
    for (int m = 0; m < 3; m++) {
        const float2* Wp  = (m == 0) ? g_wqs : (m == 1) ? g_wks : g_wvs;
        const float* bias = (m == 0) ? bq : (m == 1) ? bk : bv;
        float* dst        = (m == 0) ? Qf : (m == 1) ? Kf : Vf;

        float acc[4][4];
        #pragma unroll
        for (int i = 0; i < 4; i++)
            #pragma unroll
            for (int j = 0; j < 4; j++) acc[i][j] = 0.0f;

        mma_gemm64<16, H_STR>(H, Wp, acc, mtile, nhalf, g, tq);

        #pragma unroll
        for (int nt = 0; nt < 4; nt++) {
            int j0 = nhalf * 32 + nt * 8 + 2 * tq;
            float bj0 = bias[j0], bj1 = bias[j0 + 1];
            int r0 = mtile * 16 + g;
            dst[r0 * QKV_STR + j0]           = fmaxf(acc[nt][0] + bj0, 0.0f);
            dst[r0 * QKV_STR + j0 + 1]       = fmaxf(acc[nt][1] + bj1, 0.0f);
            dst[(r0 + 8) * QKV_STR + j0]     = fmaxf(acc[nt][2] + bj0, 0.0f);
            dst[(r0 + 8) * QKV_STR + j0 + 1] = fmaxf(acc[nt][3] + bj1, 0.0f);
        }
    }
    __syncthreads();   // Q,K,V visible; H A-reads done -> S0 may overwrite cols 64..127

    // ---- attention via tf32 mma, 2 heads per pass (round-5 code verbatim) ----
    const float rsc = 0.3535533905932738f;   // 1/sqrt(8)
    const int r0m = mtile * 16;

    #pragma unroll 1
    for (int hp = 0; hp < 4; hp++) {
        const int head = hp * 2 + hsel;
        const int hc   = head * 8;
        float* Sb      = hsel ? S1 : S0;
        const int sst  = hsel ? S1_STR : H_STR;

        // scores: S[t][s] = (Q_h @ K_h^T) * rsc, causal mask
        {
            uint32_t ah[4], al[4];
            tf32_split(Qf[(r0m + g)     * QKV_STR + hc + tq],     ah[0], al[0]);
            tf32_split(Qf[(r0m + g + 8) * QKV_STR + hc + tq],     ah[1], al[1]);
            tf32_split(Qf[(r0m + g)     * QKV_STR + hc + tq + 4], ah[2], al[2]);
            tf32_split(Qf[(r0m + g + 8) * QKV_STR + hc + tq + 4], ah[3], al[3]);
            const int ta = r0m + g, tb = ta + 8;
            #pragma unroll
            for (int nt = 0; nt < 8; nt++) {
                const int n0 = nt * 8;
                uint32_t bh[2], bl[2];
                tf32_split(Kf[(n0 + g) * QKV_STR + hc + tq],     bh[0], bl[0]);
                tf32_split(Kf[(n0 + g) * QKV_STR + hc + tq + 4], bh[1], bl[1]);
                float c[4] = {0.f, 0.f, 0.f, 0.f};
                mma8(c, ah, bh);
                mma8(c, ah, bl);
                mma8(c, al, bh);
                const int s0 = n0 + 2 * tq;
                float v0 = (s0     > ta) ? NEG_ : c[0] * rsc;
                float v1 = (s0 + 1 > ta) ? NEG_ : c[1] * rsc;
                float v2 = (s0     > tb) ? NEG_ : c[2] * rsc;
                float v3 = (s0 + 1 > tb) ? NEG_ : c[3] * rsc;
                *(float2*)&Sb[ta * sst + s0] = make_float2(v0, v1);
                *(float2*)&Sb[tb * sst + s0] = make_float2(v2, v3);
            }
        }
        __syncthreads();

        // softmax: 256 threads per problem, each handles row r2 of BOTH buffers
        {
            const int r2 = ltid >> 2, l4 = ltid & 3;
            softmax_row(S0 + r2 * H_STR, l4);
            softmax_row(S1 + r2 * S1_STR, l4);
        }
        __syncthreads();

        // AV: O[t][hc..hc+8] = P @ V_h  (8 k-steps over s)
        {
            float c[4] = {0.f, 0.f, 0.f, 0.f};
            #pragma unroll
            for (int kk = 0; kk < 8; kk++) {
                const int k0 = kk * 8;
                uint32_t ah[4], al[4], bh[2], bl[2];
                tf32_split(Sb[(r0m + g)     * sst + k0 + tq],     ah[0], al[0]);
                tf32_split(Sb[(r0m + g + 8) * sst + k0 + tq],     ah[1], al[1]);
                tf32_split(Sb[(r0m + g)     * sst + k0 + tq + 4], ah[2], al[2]);
                tf32_split(Sb[(r0m + g + 8) * sst + k0 + tq + 4], ah[3], al[3]);
                tf32_split(Vf[(k0 + tq)     * QKV_STR + hc + g],  bh[0], bl[0]);
                tf32_split(Vf[(k0 + tq + 4) * QKV_STR + hc + g],  bh[1], bl[1]);
                mma8(c, ah, bh);
                mma8(c, ah, bl);
                mma8(c, al, bh);
            }
            *(float2*)&H[(r0m + g)     * H_STR + hc + 2 * tq] = make_float2(c[0], c[1]);
            *(float2*)&H[(r0m + g + 8) * H_STR + hc + 2 * tq] = make_float2(c[2], c[3]);
        }
        __syncthreads();
    }

    // ---- FFN layer 1: U = relu(O @ W1 + b1) -> Qf ----
    {
        float acc[4][4];
        #pragma unroll
        for (int i = 0; i < 4; i++)
            #pragma unroll
            for (int j = 0; j < 4; j++) acc[i][j] = 0.0f;

        mma_gemm64<8, H_STR>(H, g_w1s, acc, mtile, nhalf, g, tq);

        __syncthreads();   // Qf (as q) reads done; O reads done
        #pragma unroll
        for (int nt = 0; nt < 4; nt++) {
            int j0 = nhalf * 32 + nt * 8 + 2 * tq;
            float bj0 = b1[j0], bj1 = b1[j0 + 1];
            int r0 = mtile * 16 + g;
            Qf[r0 * QKV_STR + j0]           = fmaxf(acc[nt][0] + bj0, 0.0f);
            Qf[r0 * QKV_STR + j0 + 1]       = fmaxf(acc[nt][1] + bj1, 0.0f);
            Qf[(r0 + 8) * QKV_STR + j0]     = fmaxf(acc[nt][2] + bj0, 0.0f);
            Qf[(r0 + 8) * QKV_STR + j0 + 1] = fmaxf(acc[nt][3] + bj1, 0.0f);
        }
    }
    __syncthreads();

    // ---- FFN layer 2: out = U @ W2 + b2 -> global ----
    {
        float acc[4][4];
        #pragma unroll
        for (int i = 0; i < 4; i++)
            #pragma unroll
            for (int j = 0; j < 4; j++) acc[i][j] = 0.0f;

        mma_gemm64<8, QKV_STR>(Qf, g_w2s, acc, mtile, nhalf, g, tq);

        #pragma unroll
        for (int nt = 0; nt < 4; nt++) {
            int j0 = nhalf * 32 + nt * 8 + 2 * tq;
            float bj0 = b2[j0], bj1 = b2[j0 + 1];
            int r0 = mtile * 16 + g;
            float* o0 = out + (((size_t)b * T_ + r0)     * N_ + n) * D_ + j0;
            float* o1 = out + (((size_t)b * T_ + r0 + 8) * N_ + n) * D_ + j0;
            o0[0] = acc[nt][0] + bj0;
            o0[1] = acc[nt][1] + bj1;
            o1[0] = acc[nt][2] + bj0;
            o1[1] = acc[nt][3] + bj1;
        }
    }
}

extern "C" void kernel_launch(void* const* d_in, const int* in_sizes, int n_in,
                              void* d_out, int out_size)
{
    (void)in_sizes; (void)n_in; (void)out_size;
    const float* x   = (const float*)d_in[0];
    const float* ste = (const float*)d_in[1];
    const float* Wq  = (const float*)d_in[2];
    const float* bq  = (const float*)d_in[3];
    const float* Wk  = (const float*)d_in[4];
    const float* bk  = (const float*)d_in[5];
    const float* Wv  = (const float*)d_in[6];
    const float* bv  = (const float*)d_in[7];
    const float* W1  = (const float*)d_in[8];
    const float* b1  = (const float*)d_in[9];
    const float* W2  = (const float*)d_in[10];
    const float* b2  = (const float*)d_in[11];
    float* out = (float*)d_out;

    const int smem_bytes = SMEM_FLOATS * sizeof(float);   // 206848
    static bool attr_set = false;
    if (!attr_set) {
        cudaFuncSetAttribute(temporal_attn_kernel,
                             cudaFuncAttributeMaxDynamicSharedMemorySize,
                             smem_bytes);
        attr_set = true;
    }
    prep_weights<<<128, 256>>>(Wq, Wk, Wv, W1, W2);
    temporal_attn_kernel<<<(B_ * N_) / 2, 512, smem_bytes>>>(
        x, ste, bq, bk, bv, b1, b2, out);
}

// round 11
// speedup vs baseline: 1.3743x; 1.3743x over previous
#include <cuda_runtime.h>
#include <cstdint>

// Problem constants
#define B_ 8
#define T_ 64
#define N_ 512
#define D_ 64
#define KH_ 8
#define NEG_ (-32767.0f)

// smem (floats), one problem per CTA (round-5 per-problem layout):
//   H  : 64 x 132 (concat(x,ste); cols 64..127 reused as score buf S0; cols 0..63 as attn out O)
//   Qf : 64 x 68  (q; reused as FFN hidden U)
//   Kf : 64 x 68
//   Vf : 64 x 68
//   S1 : 64 x 68  (second score buffer)
#define H_STR   132
#define QKV_STR 68
#define S1_STR  68
#define SMEM_FLOATS (64 * H_STR + 4 * 64 * QKV_STR)   // 25856 floats = 103424 B

// ---- tf32 helpers ----
__device__ __forceinline__ uint32_t tf32_hi(float v) {
    uint32_t h;
    asm("cvt.rna.tf32.f32 %0, %1;" : "=r"(h) : "f"(v));
    return h;
}
__device__ __forceinline__ void tf32_split(float v, uint32_t& hi, uint32_t& lo) {
    hi = tf32_hi(v);
    float l = v - __uint_as_float(hi);
    lo = tf32_hi(l);
}
__device__ __forceinline__ void mma8(float c[4], const uint32_t a[4], const uint32_t b[2]) {
    asm volatile(
        "mma.sync.aligned.m16n8k8.row.col.f32.tf32.tf32.f32 "
        "{%0,%1,%2,%3}, {%4,%5,%6,%7}, {%8,%9}, {%0,%1,%2,%3};"
        : "+f"(c[0]), "+f"(c[1]), "+f"(c[2]), "+f"(c[3])
        : "r"(a[0]), "r"(a[1]), "r"(a[2]), "r"(a[3]), "r"(b[0]), "r"(b[1]));
}

// 64xN-slab GEMM accumulate (round-5 verbatim): acc[4][4] covers rows mtile*16..+16,
// cols nhalf*32..+32. A: smem fp32 (stride ASTR), W: global fp32 [k][64]. 3-term tf32 split.
template<int KSTEPS, int ASTR>
__device__ __forceinline__ void mma_gemm64(const float* __restrict__ A,
                                           const float* __restrict__ W,
                                           float acc[4][4],
                                           int mtile, int nhalf, int g, int tq)
{
    const float* Ab = A + mtile * 16 * ASTR;
    #pragma unroll
    for (int kk = 0; kk < KSTEPS; kk++) {
        const int k0 = kk * 8;
        uint32_t ah[4], al[4];
        tf32_split(Ab[g * ASTR + k0 + tq],           ah[0], al[0]);
        tf32_split(Ab[(g + 8) * ASTR + k0 + tq],     ah[1], al[1]);
        tf32_split(Ab[g * ASTR + k0 + tq + 4],       ah[2], al[2]);
        tf32_split(Ab[(g + 8) * ASTR + k0 + tq + 4], ah[3], al[3]);

        float bv0[4], bv1[4];
        #pragma unroll
        for (int nt = 0; nt < 4; nt++) {
            const float* Wb = W + k0 * 64 + nhalf * 32 + nt * 8;
            bv0[nt] = Wb[tq * 64 + g];
            bv1[nt] = Wb[(tq + 4) * 64 + g];
        }
        #pragma unroll
        for (int nt = 0; nt < 4; nt++) {
            uint32_t bh[2], bl[2];
            tf32_split(bv0[nt], bh[0], bl[0]);
            tf32_split(bv1[nt], bh[1], bl[1]);
            mma8(acc[nt], ah, bh);
            mma8(acc[nt], ah, bl);
            mma8(acc[nt], al, bh);
        }
    }
}

// vectorized softmax: 4 lanes per row, lane l4 owns contiguous cols [l4*16, +16)
__device__ __forceinline__ void softmax_row(float* __restrict__ row, int l4) {
    float4 v[4];
    float mx = -1e30f;
    #pragma unroll
    for (int k = 0; k < 4; k++) {
        v[k] = *(float4*)&row[l4 * 16 + k * 4];
        mx = fmaxf(mx, fmaxf(fmaxf(v[k].x, v[k].y), fmaxf(v[k].z, v[k].w)));
    }
    mx = fmaxf(mx, __shfl_xor_sync(0xffffffffu, mx, 1));
    mx = fmaxf(mx, __shfl_xor_sync(0xffffffffu, mx, 2));
    float sum = 0.0f;
    #pragma unroll
    for (int k = 0; k < 4; k++) {
        v[k].x = __expf(v[k].x - mx);
        v[k].y = __expf(v[k].y - mx);
        v[k].z = __expf(v[k].z - mx);
        v[k].w = __expf(v[k].w - mx);
        sum += (v[k].x + v[k].y) + (v[k].z + v[k].w);
    }
    sum += __shfl_xor_sync(0xffffffffu, sum, 1);
    sum += __shfl_xor_sync(0xffffffffu, sum, 2);
    float inv = 1.0f / sum;
    #pragma unroll
    for (int k = 0; k < 4; k++) {
        v[k].x *= inv; v[k].y *= inv; v[k].z *= inv; v[k].w *= inv;
        *(float4*)&row[l4 * 16 + k * 4] = v[k];
    }
}

__global__ __launch_bounds__(256, 2)
void temporal_attn_kernel(
    const float* __restrict__ x,  const float* __restrict__ ste,
    const float* __restrict__ Wq, const float* __restrict__ bq,
    const float* __restrict__ Wk, const float* __restrict__ bk,
    const float* __restrict__ Wv, const float* __restrict__ bv,
    const float* __restrict__ W1, const float* __restrict__ b1,
    const float* __restrict__ W2, const float* __restrict__ b2,
    float* __restrict__ out)
{
    extern __shared__ float sm[];
    const int tid = threadIdx.x;      // 0..255, one problem per CTA

    const int p = blockIdx.x;
    const int n = p & (N_ - 1);
    const int b = p >> 9;

    float* H  = sm;
    float* Qf = H  + 64 * H_STR;
    float* Kf = Qf + 64 * QKV_STR;
    float* Vf = Kf + 64 * QKV_STR;
    float* S1 = Vf + 64 * QKV_STR;
    float* S0 = H + 64;               // score buf 0: H cols 64..127 (stride 132)

    // ---- load H = concat(x, ste): 64 x 128, float4 ----
    {
        const float* xb = x   + ((size_t)((size_t)b * T_) * N_ + n) * D_;
        const float* sb = ste + ((size_t)((size_t)b * T_) * N_ + n) * D_;
        #pragma unroll
        for (int i = 0; i < 4; i++) {
            int idx = tid + i * 256;
            int t = idx >> 4, f4 = (idx & 15) << 2;
            size_t g = (size_t)t * (N_ * D_) + f4;
            *(float4*)&H[t * H_STR + f4]      = *(const float4*)&xb[g];
            *(float4*)&H[t * H_STR + 64 + f4] = *(const float4*)&sb[g];
        }
    }
    __syncthreads();

    // warp/lane mapping
    const int lane  = tid & 31;
    const int wl    = tid >> 5;       // warp 0..7
    const int g     = lane >> 2;
    const int tq    = lane & 3;
    const int mtile = wl & 3;
    const int nhalf = wl >> 2;
    const int hsel  = wl >> 2;

    // ---- QKV projections (3 passes): relu(H[64x128] @ W[128x64] + b) ----
    #pragma unroll 1
    for (int m = 0; m < 3; m++) {
        const float* W    = (m == 0) ? Wq : (m == 1) ? Wk : Wv;
        const float* bias = (m == 0) ? bq : (m == 1) ? bk : bv;
        float* dst        = (m == 0) ? Qf : (m == 1) ? Kf : Vf;

        float acc[4][4];
        #pragma unroll
        for (int i = 0; i < 4; i++)
            #pragma unroll
            for (int j = 0; j < 4; j++) acc[i][j] = 0.0f;

        mma_gemm64<16, H_STR>(H, W, acc, mtile, nhalf, g, tq);

        #pragma unroll
        for (int nt = 0; nt < 4; nt++) {
            int j0 = nhalf * 32 + nt * 8 + 2 * tq;
            float bj0 = bias[j0], bj1 = bias[j0 + 1];
            int r0 = mtile * 16 + g;
            dst[r0 * QKV_STR + j0]           = fmaxf(acc[nt][0] + bj0, 0.0f);
            dst[r0 * QKV_STR + j0 + 1]       = fmaxf(acc[nt][1] + bj1, 0.0f);
            dst[(r0 + 8) * QKV_STR + j0]     = fmaxf(acc[nt][2] + bj0, 0.0f);
            dst[(r0 + 8) * QKV_STR + j0 + 1] = fmaxf(acc[nt][3] + bj1, 0.0f);
        }
    }
    __syncthreads();   // Q,K,V visible; H A-reads done -> S0 may overwrite cols 64..127

    // ---- attention via tf32 mma, 2 heads per pass ----
    const float rsc = 0.3535533905932738f;   // 1/sqrt(8)
    const int r0m = mtile * 16;

    #pragma unroll 1
    for (int hp = 0; hp < 4; hp++) {
        const int head = hp * 2 + hsel;
        const int hc   = head * 8;
        float* Sb      = hsel ? S1 : S0;
        const int sst  = hsel ? S1_STR : H_STR;

        // scores: S[t][s] = (Q_h @ K_h^T) * rsc, causal mask
        {
            uint32_t ah[4], al[4];
            tf32_split(Qf[(r0m + g)     * QKV_STR + hc + tq],     ah[0], al[0]);
            tf32_split(Qf[(r0m + g + 8) * QKV_STR + hc + tq],     ah[1], al[1]);
            tf32_split(Qf[(r0m + g)     * QKV_STR + hc + tq + 4], ah[2], al[2]);
            tf32_split(Qf[(r0m + g + 8) * QKV_STR + hc + tq + 4], ah[3], al[3]);
            const int ta = r0m + g, tb = ta + 8;
            #pragma unroll
            for (int nt = 0; nt < 8; nt++) {
                const int n0 = nt * 8;
                uint32_t bh[2], bl[2];
                tf32_split(Kf[(n0 + g) * QKV_STR + hc + tq],     bh[0], bl[0]);
                tf32_split(Kf[(n0 + g) * QKV_STR + hc + tq + 4], bh[1], bl[1]);
                float c[4] = {0.f, 0.f, 0.f, 0.f};
                mma8(c, ah, bh);
                mma8(c, ah, bl);
                mma8(c, al, bh);
                const int s0 = n0 + 2 * tq;
                float v0 = (s0     > ta) ? NEG_ : c[0] * rsc;
                float v1 = (s0 + 1 > ta) ? NEG_ : c[1] * rsc;
                float v2 = (s0     > tb) ? NEG_ : c[2] * rsc;
                float v3 = (s0 + 1 > tb) ? NEG_ : c[3] * rsc;
                *(float2*)&Sb[ta * sst + s0] = make_float2(v0, v1);
                *(float2*)&Sb[tb * sst + s0] = make_float2(v2, v3);
            }
        }
        __syncthreads();

        // softmax: each thread handles row r2 of BOTH buffers (vectorized)
        {
            const int r2 = tid >> 2, l4 = tid & 3;
            softmax_row(S0 + r2 * H_STR, l4);
            softmax_row(S1 + r2 * S1_STR, l4);
        }
        __syncthreads();

        // AV: O[t][hc..hc+8] = P @ V_h  (8 k-steps over s)
        {
            float c[4] = {0.f, 0.f, 0.f, 0.f};
            #pragma unroll
            for (int kk = 0; kk < 8; kk++) {
                const int k0 = kk * 8;
                uint32_t ah[4], al[4], bh[2], bl[2];
                tf32_split(Sb[(r0m + g)     * sst + k0 + tq],     ah[0], al[0]);
                tf32_split(Sb[(r0m + g + 8) * sst + k0 + tq],     ah[1], al[1]);
                tf32_split(Sb[(r0m + g)     * sst + k0 + tq + 4], ah[2], al[2]);
                tf32_split(Sb[(r0m + g + 8) * sst + k0 + tq + 4], ah[3], al[3]);
                tf32_split(Vf[(k0 + tq)     * QKV_STR + hc + g],  bh[0], bl[0]);
                tf32_split(Vf[(k0 + tq + 4) * QKV_STR + hc + g],  bh[1], bl[1]);
                mma8(c, ah, bh);
                mma8(c, ah, bl);
                mma8(c, al, bh);
            }
            *(float2*)&H[(r0m + g)     * H_STR + hc + 2 * tq] = make_float2(c[0], c[1]);
            *(float2*)&H[(r0m + g + 8) * H_STR + hc + 2 * tq] = make_float2(c[2], c[3]);
        }
        __syncthreads();
    }

    // ---- FFN layer 1: U = relu(O @ W1 + b1) -> Qf ----
    {
        float acc[4][4];
        #pragma unroll
        for (int i = 0; i < 4; i++)
            #pragma unroll
            for (int j = 0; j < 4; j++) acc[i][j] = 0.0f;

        mma_gemm64<8, H_STR>(H, W1, acc, mtile, nhalf, g, tq);

        __syncthreads();   // Qf (as q) reads done; O reads done
        #pragma unroll
        for (int nt = 0; nt < 4; nt++) {
            int j0 = nhalf * 32 + nt * 8 + 2 * tq;
            float bj0 = b1[j0], bj1 = b1[j0 + 1];
            int r0 = mtile * 16 + g;
            Qf[r0 * QKV_STR + j0]           = fmaxf(acc[nt][0] + bj0, 0.0f);
            Qf[r0 * QKV_STR + j0 + 1]       = fmaxf(acc[nt][1] + bj1, 0.0f);
            Qf[(r0 + 8) * QKV_STR + j0]     = fmaxf(acc[nt][2] + bj0, 0.0f);
            Qf[(r0 + 8) * QKV_STR + j0 + 1] = fmaxf(acc[nt][3] + bj1, 0.0f);
        }
    }
    __syncthreads();

    // ---- FFN layer 2: out = U @ W2 + b2 -> global ----
    {
        float acc[4][4];
        #pragma unroll
        for (int i = 0; i < 4; i++)
            #pragma unroll
            for (int j = 0; j < 4; j++) acc[i][j] = 0.0f;

        mma_gemm64<8, QKV_STR>(Qf, W2, acc, mtile, nhalf, g, tq);

        #pragma unroll
        for (int nt = 0; nt < 4; nt++) {
            int j0 = nhalf * 32 + nt * 8 + 2 * tq;
            float bj0 = b2[j0], bj1 = b2[j0 + 1];
            int r0 = mtile * 16 + g;
            float* o0 = out + (((size_t)b * T_ + r0)     * N_ + n) * D_ + j0;
            float* o1 = out + (((size_t)b * T_ + r0 + 8) * N_ + n) * D_ + j0;
            o0[0] = acc[nt][0] + bj0;
            o0[1] = acc[nt][1] + bj1;
            o1[0] = acc[nt][2] + bj0;
            o1[1] = acc[nt][3] + bj1;
        }
    }
}

extern "C" void kernel_launch(void* const* d_in, const int* in_sizes, int n_in,
                              void* d_out, int out_size)
{
    (void)in_sizes; (void)n_in; (void)out_size;
    const float* x   = (const float*)d_in[0];
    const float* ste = (const float*)d_in[1];
    const float* Wq  = (const float*)d_in[2];
    const float* bq  = (const float*)d_in[3];
    const float* Wk  = (const float*)d_in[4];
    const float* bk  = (const float*)d_in[5];
    const float* Wv  = (const float*)d_in[6];
    const float* bv  = (const float*)d_in[7];
    const float* W1  = (const float*)d_in[8];
    const float* b1  = (const float*)d_in[9];
    const float* W2  = (const float*)d_in[10];
    const float* b2  = (const float*)d_in[11];
    float* out = (float*)d_out;

    const int smem_bytes = SMEM_FLOATS * sizeof(float);   // 103424
    static bool attr_set = false;
    if (!attr_set) {
        cudaFuncSetAttribute(temporal_attn_kernel,
                             cudaFuncAttributeMaxDynamicSharedMemorySize,
                             smem_bytes);
        attr_set = true;
    }
    temporal_attn_kernel<<<B_ * N_, 256, smem_bytes>>>(
        x, ste, Wq, bq, Wk, bk, Wv, bv, W1, b1, W2, b2, out);
}

// round 12
// speedup vs baseline: 1.5917x; 1.1581x over previous
#include <cuda_runtime.h>
#include <cstdint>

// Problem constants
#define B_ 8
#define T_ 64
#define N_ 512
#define D_ 64
#define KH_ 8
#define NEG_ (-32767.0f)

// smem (floats), one problem per CTA:
//   H  : 64 x 132 (concat(x,ste); cols 64..127 reused as score buf S0; cols 0..63 as attn out O)
//   Qf : 64 x 68  (q pre-scaled by 1/sqrt(d); reused as FFN hidden U)
//   Kf : 64 x 68
//   Vf : 64 x 68
//   S1 : 64 x 68  (second score buffer)
#define H_STR   132
#define QKV_STR 68
#define S1_STR  68
#define SMEM_FLOATS (64 * H_STR + 4 * 64 * QKV_STR)   // 25856 floats = 103424 B

// ---- tf32 helpers: mask-based split (no cvt) ----
// hi: low 13 mantissa bits zeroed -> exactly representable in tf32 (HW ingestion exact).
// lo = v - hi exactly; fed raw, HW rounds/truncates it (error <= 2^-21 * |v| total).
__device__ __forceinline__ void tf32_split(float v, uint32_t& hi, uint32_t& lo) {
    hi = __float_as_uint(v) & 0xffffe000u;
    lo = __float_as_uint(v - __uint_as_float(hi));
}
__device__ __forceinline__ void mma8(float c[4], const uint32_t a[4], const uint32_t b[2]) {
    asm volatile(
        "mma.sync.aligned.m16n8k8.row.col.f32.tf32.tf32.f32 "
        "{%0,%1,%2,%3}, {%4,%5,%6,%7}, {%8,%9}, {%0,%1,%2,%3};"
        : "+f"(c[0]), "+f"(c[1]), "+f"(c[2]), "+f"(c[3])
        : "r"(a[0]), "r"(a[1]), "r"(a[2]), "r"(a[3]), "r"(b[0]), "r"(b[1]));
}

// 64xN-slab GEMM accumulate: acc[4][4] covers rows mtile*16..+16, cols nhalf*32..+32
// A: smem fp32 (stride ASTR), W: global fp32 [k][64] row-major. 3-term tf32 split.
template<int KSTEPS, int ASTR>
__device__ __forceinline__ void mma_gemm64(const float* __restrict__ A,
                                           const float* __restrict__ W,
                                           float acc[4][4],
                                           int mtile, int nhalf, int g, int tq)
{
    const float* Ab = A + mtile * 16 * ASTR;
    #pragma unroll
    for (int kk = 0; kk < KSTEPS; kk++) {
        const int k0 = kk * 8;
        uint32_t ah[4], al[4];
        tf32_split(Ab[g * ASTR + k0 + tq],           ah[0], al[0]);
        tf32_split(Ab[(g + 8) * ASTR + k0 + tq],     ah[1], al[1]);
        tf32_split(Ab[g * ASTR + k0 + tq + 4],       ah[2], al[2]);
        tf32_split(Ab[(g + 8) * ASTR + k0 + tq + 4], ah[3], al[3]);

        float bv0[4], bv1[4];
        #pragma unroll
        for (int nt = 0; nt < 4; nt++) {
            const float* Wb = W + k0 * 64 + nhalf * 32 + nt * 8;
            bv0[nt] = Wb[tq * 64 + g];
            bv1[nt] = Wb[(tq + 4) * 64 + g];
        }
        #pragma unroll
        for (int nt = 0; nt < 4; nt++) {
            uint32_t bh[2], bl[2];
            tf32_split(bv0[nt], bh[0], bl[0]);
            tf32_split(bv1[nt], bh[1], bl[1]);
            mma8(acc[nt], ah, bh);
            mma8(acc[nt], ah, bl);
            mma8(acc[nt], al, bh);
        }
    }
}

// vectorized softmax: 4 lanes per row, lane l4 owns contiguous cols [l4*16, +16)
__device__ __forceinline__ void softmax_row(float* __restrict__ row, int l4) {
    float4 v[4];
    float mx = -1e30f;
    #pragma unroll
    for (int k = 0; k < 4; k++) {
        v[k] = *(float4*)&row[l4 * 16 + k * 4];
        mx = fmaxf(mx, fmaxf(fmaxf(v[k].x, v[k].y), fmaxf(v[k].z, v[k].w)));
    }
    mx = fmaxf(mx, __shfl_xor_sync(0xffffffffu, mx, 1));
    mx = fmaxf(mx, __shfl_xor_sync(0xffffffffu, mx, 2));
    float sum = 0.0f;
    #pragma unroll
    for (int k = 0; k < 4; k++) {
        v[k].x = __expf(v[k].x - mx);
        v[k].y = __expf(v[k].y - mx);
        v[k].z = __expf(v[k].z - mx);
        v[k].w = __expf(v[k].w - mx);
        sum += (v[k].x + v[k].y) + (v[k].z + v[k].w);
    }
    sum += __shfl_xor_sync(0xffffffffu, sum, 1);
    sum += __shfl_xor_sync(0xffffffffu, sum, 2);
    float inv = 1.0f / sum;
    #pragma unroll
    for (int k = 0; k < 4; k++) {
        v[k].x *= inv; v[k].y *= inv; v[k].z *= inv; v[k].w *= inv;
        *(float4*)&row[l4 * 16 + k * 4] = v[k];
    }
}

__global__ __launch_bounds__(256, 2)
void temporal_attn_kernel(
    const float* __restrict__ x,  const float* __restrict__ ste,
    const float* __restrict__ Wq, const float* __restrict__ bq,
    const float* __restrict__ Wk, const float* __restrict__ bk,
    const float* __restrict__ Wv, const float* __restrict__ bv,
    const float* __restrict__ W1, const float* __restrict__ b1,
    const float* __restrict__ W2, const float* __restrict__ b2,
    float* __restrict__ out)
{
    extern __shared__ float sm[];
    const int tid = threadIdx.x;      // 0..255, one problem per CTA

    const int p = blockIdx.x;
    const int n = p & (N_ - 1);
    const int b = p >> 9;

    float* H  = sm;
    float* Qf = H  + 64 * H_STR;
    float* Kf = Qf + 64 * QKV_STR;
    float* Vf = Kf + 64 * QKV_STR;
    float* S1 = Vf + 64 * QKV_STR;
    float* S0 = H + 64;               // score buf 0: H cols 64..127 (stride 132)

    // ---- load H = concat(x, ste): 64 x 128, float4 ----
    {
        const float* xb = x   + ((size_t)((size_t)b * T_) * N_ + n) * D_;
        const float* sb = ste + ((size_t)((size_t)b * T_) * N_ + n) * D_;
        #pragma unroll
        for (int i = 0; i < 4; i++) {
            int idx = tid + i * 256;
            int t = idx >> 4, f4 = (idx & 15) << 2;
            size_t g = (size_t)t * (N_ * D_) + f4;
            *(float4*)&H[t * H_STR + f4]      = *(const float4*)&xb[g];
            *(float4*)&H[t * H_STR + 64 + f4] = *(const float4*)&sb[g];
        }
    }
    __syncthreads();

    // warp/lane mapping
    const int lane  = tid & 31;
    const int wl    = tid >> 5;       // warp 0..7
    const int g     = lane >> 2;
    const int tq    = lane & 3;
    const int mtile = wl & 3;
    const int nhalf = wl >> 2;
    const int hsel  = wl >> 2;

    const float rsc = 0.3535533905932738f;   // 1/sqrt(8)

    // ---- QKV projections (3 passes): relu(H[64x128] @ W[128x64] + b) ----
    // Q is pre-scaled by rsc at the epilogue (relu(v)*rsc == relu(v*rsc), rsc>0).
    #pragma unroll 1
    for (int m = 0; m < 3; m++) {
        const float* W    = (m == 0) ? Wq : (m == 1) ? Wk : Wv;
        const float* bias = (m == 0) ? bq : (m == 1) ? bk : bv;
        float* dst        = (m == 0) ? Qf : (m == 1) ? Kf : Vf;
        const float sc    = (m == 0) ? rsc : 1.0f;

        float acc[4][4];
        #pragma unroll
        for (int i = 0; i < 4; i++)
            #pragma unroll
            for (int j = 0; j < 4; j++) acc[i][j] = 0.0f;

        mma_gemm64<16, H_STR>(H, W, acc, mtile, nhalf, g, tq);

        #pragma unroll
        for (int nt = 0; nt < 4; nt++) {
            int j0 = nhalf * 32 + nt * 8 + 2 * tq;
            float bj0 = bias[j0], bj1 = bias[j0 + 1];
            int r0 = mtile * 16 + g;
            dst[r0 * QKV_STR + j0]           = fmaxf(acc[nt][0] + bj0, 0.0f) * sc;
            dst[r0 * QKV_STR + j0 + 1]       = fmaxf(acc[nt][1] + bj1, 0.0f) * sc;
            dst[(r0 + 8) * QKV_STR + j0]     = fmaxf(acc[nt][2] + bj0, 0.0f) * sc;
            dst[(r0 + 8) * QKV_STR + j0 + 1] = fmaxf(acc[nt][3] + bj1, 0.0f) * sc;
        }
    }
    __syncthreads();   // Q,K,V visible; H A-reads done -> S0 may overwrite cols 64..127

    // ---- attention via tf32 mma, 2 heads per pass ----
    const int r0m = mtile * 16;

    #pragma unroll 1
    for (int hp = 0; hp < 4; hp++) {
        const int head = hp * 2 + hsel;
        const int hc   = head * 8;
        float* Sb      = hsel ? S1 : S0;
        const int sst  = hsel ? S1_STR : H_STR;

        // scores: S[t][s] = q~[t]·k[s], causal mask (q~ pre-scaled by rsc)
        {
            uint32_t ah[4], al[4];
            tf32_split(Qf[(r0m + g)     * QKV_STR + hc + tq],     ah[0], al[0]);
            tf32_split(Qf[(r0m + g + 8) * QKV_STR + hc + tq],     ah[1], al[1]);
            tf32_split(Qf[(r0m + g)     * QKV_STR + hc + tq + 4], ah[2], al[2]);
            tf32_split(Qf[(r0m + g + 8) * QKV_STR + hc + tq + 4], ah[3], al[3]);
            const int ta = r0m + g, tb = ta + 8;
            #pragma unroll
            for (int nt = 0; nt < 8; nt++) {
                const int n0 = nt * 8;
                uint32_t bh[2], bl[2];
                tf32_split(Kf[(n0 + g) * QKV_STR + hc + tq],     bh[0], bl[0]);
                tf32_split(Kf[(n0 + g) * QKV_STR + hc + tq + 4], bh[1], bl[1]);
                float c[4] = {0.f, 0.f, 0.f, 0.f};
                mma8(c, ah, bh);
                mma8(c, ah, bl);
                mma8(c, al, bh);
                const int s0 = n0 + 2 * tq;
                float v0 = (s0     > ta) ? NEG_ : c[0];
                float v1 = (s0 + 1 > ta) ? NEG_ : c[1];
                float v2 = (s0     > tb) ? NEG_ : c[2];
                float v3 = (s0 + 1 > tb) ? NEG_ : c[3];
                *(float2*)&Sb[ta * sst + s0] = make_float2(v0, v1);
                *(float2*)&Sb[tb * sst + s0] = make_float2(v2, v3);
            }
        }
        __syncthreads();

        // softmax: each thread handles row r2 of BOTH buffers (vectorized)
        {
            const int r2 = tid >> 2, l4 = tid & 3;
            softmax_row(S0 + r2 * H_STR, l4);
            softmax_row(S1 + r2 * S1_STR, l4);
        }
        __syncthreads();

        // AV: O[t][hc..hc+8] = P @ V_h  (8 k-steps over s)
        {
            float c[4] = {0.f, 0.f, 0.f, 0.f};
            #pragma unroll
            for (int kk = 0; kk < 8; kk++) {
                const int k0 = kk * 8;
                uint32_t ah[4], al[4], bh[2], bl[2];
                tf32_split(Sb[(r0m + g)     * sst + k0 + tq],     ah[0], al[0]);
                tf32_split(Sb[(r0m + g + 8) * sst + k0 + tq],     ah[1], al[1]);
                tf32_split(Sb[(r0m + g)     * sst + k0 + tq + 4], ah[2], al[2]);
                tf32_split(Sb[(r0m + g + 8) * sst + k0 + tq + 4], ah[3], al[3]);
                tf32_split(Vf[(k0 + tq)     * QKV_STR + hc + g],  bh[0], bl[0]);
                tf32_split(Vf[(k0 + tq + 4) * QKV_STR + hc + g],  bh[1], bl[1]);
                mma8(c, ah, bh);
                mma8(c, ah, bl);
                mma8(c, al, bh);
            }
            *(float2*)&H[(r0m + g)     * H_STR + hc + 2 * tq] = make_float2(c[0], c[1]);
            *(float2*)&H[(r0m + g + 8) * H_STR + hc + 2 * tq] = make_float2(c[2], c[3]);
        }
        __syncthreads();
    }

    // ---- FFN layer 1: U = relu(O @ W1 + b1) -> Qf ----
    {
        float acc[4][4];
        #pragma unroll
        for (int i = 0; i < 4; i++)
            #pragma unroll
            for (int j = 0; j < 4; j++) acc[i][j] = 0.0f;

        mma_gemm64<8, H_STR>(H, W1, acc, mtile, nhalf, g, tq);

        __syncthreads();   // Qf (as q) reads done; O reads done
        #pragma unroll
        for (int nt = 0; nt < 4; nt++) {
            int j0 = nhalf * 32 + nt * 8 + 2 * tq;
            float bj0 = b1[j0], bj1 = b1[j0 + 1];
            int r0 = mtile * 16 + g;
            Qf[r0 * QKV_STR + j0]           = fmaxf(acc[nt][0] + bj0, 0.0f);
            Qf[r0 * QKV_STR + j0 + 1]       = fmaxf(acc[nt][1] + bj1, 0.0f);
            Qf[(r0 + 8) * QKV_STR + j0]     = fmaxf(acc[nt][2] + bj0, 0.0f);
            Qf[(r0 + 8) * QKV_STR + j0 + 1] = fmaxf(acc[nt][3] + bj1, 0.0f);
        }
    }
    __syncthreads();

    // ---- FFN layer 2: out = U @ W2 + b2 -> global ----
    {
        float acc[4][4];
        #pragma unroll
        for (int i = 0; i < 4; i++)
            #pragma unroll
            for (int j = 0; j < 4; j++) acc[i][j] = 0.0f;

        mma_gemm64<8, QKV_STR>(Qf, W2, acc, mtile, nhalf, g, tq);

        #pragma unroll
        for (int nt = 0; nt < 4; nt++) {
            int j0 = nhalf * 32 + nt * 8 + 2 * tq;
            float bj0 = b2[j0], bj1 = b2[j0 + 1];
            int r0 = mtile * 16 + g;
            float* o0 = out + (((size_t)b * T_ + r0)     * N_ + n) * D_ + j0;
            float* o1 = out + (((size_t)b * T_ + r0 + 8) * N_ + n) * D_ + j0;
            o0[0] = acc[nt][0] + bj0;
            o0[1] = acc[nt][1] + bj1;
            o1[0] = acc[nt][2] + bj0;
            o1[1] = acc[nt][3] + bj1;
        }
    }
}

extern "C" void kernel_launch(void* const* d_in, const int* in_sizes, int n_in,
                              void* d_out, int out_size)
{
    (void)in_sizes; (void)n_in; (void)out_size;
    const float* x   = (const float*)d_in[0];
    const float* ste = (const float*)d_in[1];
    const float* Wq  = (const float*)d_in[2];
    const float* bq  = (const float*)d_in[3];
    const float* Wk  = (const float*)d_in[4];
    const float* bk  = (const float*)d_in[5];
    const float* Wv  = (const float*)d_in[6];
    const float* bv  = (const float*)d_in[7];
    const float* W1  = (const float*)d_in[8];
    const float* b1  = (const float*)d_in[9];
    const float* W2  = (const float*)d_in[10];
    const float* b2  = (const float*)d_in[11];
    float* out = (float*)d_out;

    const int smem_bytes = SMEM_FLOATS * sizeof(float);   // 103424
    static bool attr_set = false;
    if (!attr_set) {
        cudaFuncSetAttribute(temporal_attn_kernel,
                             cudaFuncAttributeMaxDynamicSharedMemorySize,
                             smem_bytes);
        attr_set = true;
    }
    temporal_attn_kernel<<<B_ * N_, 256, smem_bytes>>>(
        x, ste, Wq, bq, Wk, bk, Wv, bv, W1, b1, W2, b2, out);
}

// round 13
// speedup vs baseline: 1.8721x; 1.1762x over previous
#include <cuda_runtime.h>
#include <cstdint>

// Problem constants
#define B_ 8
#define T_ 64
#define N_ 512
#define D_ 64
#define KH_ 8
#define NEG_ (-32767.0f)

// smem (floats), one problem per CTA:
//   H  : 64 x 132 (concat(x,ste); cols 0..63 reused as attn out O)
//   Qf : 64 x 68  (q pre-scaled by 1/sqrt(d); reused as FFN hidden U)
//   Kf : 64 x 68
//   Vf : 64 x 68
#define H_STR   132
#define QKV_STR 68
#define SMEM_FLOATS (64 * H_STR + 3 * 64 * QKV_STR)   // 21504 floats = 86016 B

// ---- tf32 helpers: mask-based split (no cvt) ----
__device__ __forceinline__ void tf32_split(float v, uint32_t& hi, uint32_t& lo) {
    hi = __float_as_uint(v) & 0xffffe000u;
    lo = __float_as_uint(v - __uint_as_float(hi));
}
__device__ __forceinline__ void mma8(float c[4], const uint32_t a[4], const uint32_t b[2]) {
    asm volatile(
        "mma.sync.aligned.m16n8k8.row.col.f32.tf32.tf32.f32 "
        "{%0,%1,%2,%3}, {%4,%5,%6,%7}, {%8,%9}, {%0,%1,%2,%3};"
        : "+f"(c[0]), "+f"(c[1]), "+f"(c[2]), "+f"(c[3])
        : "r"(a[0]), "r"(a[1]), "r"(a[2]), "r"(a[3]), "r"(b[0]), "r"(b[1]));
}

// 64xN-slab GEMM accumulate: acc[4][4] covers rows mtile*16..+16, cols nhalf*32..+32
template<int KSTEPS, int ASTR>
__device__ __forceinline__ void mma_gemm64(const float* __restrict__ A,
                                           const float* __restrict__ W,
                                           float acc[4][4],
                                           int mtile, int nhalf, int g, int tq)
{
    const float* Ab = A + mtile * 16 * ASTR;
    #pragma unroll
    for (int kk = 0; kk < KSTEPS; kk++) {
        const int k0 = kk * 8;
        uint32_t ah[4], al[4];
        tf32_split(Ab[g * ASTR + k0 + tq],           ah[0], al[0]);
        tf32_split(Ab[(g + 8) * ASTR + k0 + tq],     ah[1], al[1]);
        tf32_split(Ab[g * ASTR + k0 + tq + 4],       ah[2], al[2]);
        tf32_split(Ab[(g + 8) * ASTR + k0 + tq + 4], ah[3], al[3]);

        float bv0[4], bv1[4];
        #pragma unroll
        for (int nt = 0; nt < 4; nt++) {
            const float* Wb = W + k0 * 64 + nhalf * 32 + nt * 8;
            bv0[nt] = Wb[tq * 64 + g];
            bv1[nt] = Wb[(tq + 4) * 64 + g];
        }
        #pragma unroll
        for (int nt = 0; nt < 4; nt++) {
            uint32_t bh[2], bl[2];
            tf32_split(bv0[nt], bh[0], bl[0]);
            tf32_split(bv1[nt], bh[1], bl[1]);
            mma8(acc[nt], ah, bh);
            mma8(acc[nt], ah, bl);
            mma8(acc[nt], al, bh);
        }
    }
}

// register softmax over one 64-wide row held as 16 values/lane across 4 tq-lanes
__device__ __forceinline__ void softmax_reg16(float* __restrict__ v) {
    float mx = v[0];
    #pragma unroll
    for (int k = 1; k < 16; k++) mx = fmaxf(mx, v[k]);
    mx = fmaxf(mx, __shfl_xor_sync(0xffffffffu, mx, 1));
    mx = fmaxf(mx, __shfl_xor_sync(0xffffffffu, mx, 2));
    float sum = 0.0f;
    #pragma unroll
    for (int k = 0; k < 16; k++) { v[k] = __expf(v[k] - mx); sum += v[k]; }
    sum += __shfl_xor_sync(0xffffffffu, sum, 1);
    sum += __shfl_xor_sync(0xffffffffu, sum, 2);
    float inv = 1.0f / sum;
    #pragma unroll
    for (int k = 0; k < 16; k++) v[k] *= inv;
}

__global__ __launch_bounds__(256, 2)
void temporal_attn_kernel(
    const float* __restrict__ x,  const float* __restrict__ ste,
    const float* __restrict__ Wq, const float* __restrict__ bq,
    const float* __restrict__ Wk, const float* __restrict__ bk,
    const float* __restrict__ Wv, const float* __restrict__ bv,
    const float* __restrict__ W1, const float* __restrict__ b1,
    const float* __restrict__ W2, const float* __restrict__ b2,
    float* __restrict__ out)
{
    extern __shared__ float sm[];
    const int tid = threadIdx.x;      // 0..255, one problem per CTA

    const int p = blockIdx.x;
    const int n = p & (N_ - 1);
    const int b = p >> 9;

    float* H  = sm;
    float* Qf = H  + 64 * H_STR;
    float* Kf = Qf + 64 * QKV_STR;
    float* Vf = Kf + 64 * QKV_STR;

    // ---- load H = concat(x, ste): 64 x 128, float4 ----
    {
        const float* xb = x   + ((size_t)((size_t)b * T_) * N_ + n) * D_;
        const float* sb = ste + ((size_t)((size_t)b * T_) * N_ + n) * D_;
        #pragma unroll
        for (int i = 0; i < 4; i++) {
            int idx = tid + i * 256;
            int t = idx >> 4, f4 = (idx & 15) << 2;
            size_t g = (size_t)t * (N_ * D_) + f4;
            *(float4*)&H[t * H_STR + f4]      = *(const float4*)&xb[g];
            *(float4*)&H[t * H_STR + 64 + f4] = *(const float4*)&sb[g];
        }
    }
    __syncthreads();

    // warp/lane mapping
    const int lane  = tid & 31;
    const int wl    = tid >> 5;       // warp 0..7
    const int g     = lane >> 2;
    const int tq    = lane & 3;
    const int mtile = wl & 3;
    const int nhalf = wl >> 2;
    const int hsel  = wl >> 2;

    const float rsc = 0.3535533905932738f;   // 1/sqrt(8)

    // ---- QKV projections (3 passes): relu(H[64x128] @ W[128x64] + b) ----
    // Q is pre-scaled by rsc at the epilogue.
    #pragma unroll 1
    for (int m = 0; m < 3; m++) {
        const float* W    = (m == 0) ? Wq : (m == 1) ? Wk : Wv;
        const float* bias = (m == 0) ? bq : (m == 1) ? bk : bv;
        float* dst        = (m == 0) ? Qf : (m == 1) ? Kf : Vf;
        const float sc    = (m == 0) ? rsc : 1.0f;

        float acc[4][4];
        #pragma unroll
        for (int i = 0; i < 4; i++)
            #pragma unroll
            for (int j = 0; j < 4; j++) acc[i][j] = 0.0f;

        mma_gemm64<16, H_STR>(H, W, acc, mtile, nhalf, g, tq);

        #pragma unroll
        for (int nt = 0; nt < 4; nt++) {
            int j0 = nhalf * 32 + nt * 8 + 2 * tq;
            float bj0 = bias[j0], bj1 = bias[j0 + 1];
            int r0 = mtile * 16 + g;
            dst[r0 * QKV_STR + j0]           = fmaxf(acc[nt][0] + bj0, 0.0f) * sc;
            dst[r0 * QKV_STR + j0 + 1]       = fmaxf(acc[nt][1] + bj1, 0.0f) * sc;
            dst[(r0 + 8) * QKV_STR + j0]     = fmaxf(acc[nt][2] + bj0, 0.0f) * sc;
            dst[(r0 + 8) * QKV_STR + j0 + 1] = fmaxf(acc[nt][3] + bj1, 0.0f) * sc;
        }
    }
    __syncthreads();   // Q,K,V visible; attention is barrier-free from here

    // ---- attention: fully register-resident per warp ----
    const int r0m  = mtile * 16;
    const int base4 = lane & ~3;            // g*4
    const int srcA  = base4 + (tq >> 1);    // shfl source for col k0+tq
    const int srcB  = srcA + 2;             // shfl source for col k0+tq+4

    #pragma unroll 1
    for (int hp = 0; hp < 4; hp++) {
        const int head = hp * 2 + hsel;
        const int hc   = head * 8;

        float p0[16], p1[16];   // rows ta=r0m+g and tb=ta+8, cols {n0+2tq, n0+2tq+1} per 8-group

        // scores: C-fragments, causal mask applied in registers
        {
            uint32_t ah[4], al[4];
            tf32_split(Qf[(r0m + g)     * QKV_STR + hc + tq],     ah[0], al[0]);
            tf32_split(Qf[(r0m + g + 8) * QKV_STR + hc + tq],     ah[1], al[1]);
            tf32_split(Qf[(r0m + g)     * QKV_STR + hc + tq + 4], ah[2], al[2]);
            tf32_split(Qf[(r0m + g + 8) * QKV_STR + hc + tq + 4], ah[3], al[3]);
            const int ta = r0m + g, tb = ta + 8;
            #pragma unroll
            for (int nt = 0; nt < 8; nt++) {
                const int n0 = nt * 8;
                uint32_t bh[2], bl[2];
                tf32_split(Kf[(n0 + g) * QKV_STR + hc + tq],     bh[0], bl[0]);
                tf32_split(Kf[(n0 + g) * QKV_STR + hc + tq + 4], bh[1], bl[1]);
                float c[4] = {0.f, 0.f, 0.f, 0.f};
                mma8(c, ah, bh);
                mma8(c, ah, bl);
                mma8(c, al, bh);
                const int s0 = n0 + 2 * tq;
                p0[2 * nt]     = (s0     > ta) ? NEG_ : c[0];
                p0[2 * nt + 1] = (s0 + 1 > ta) ? NEG_ : c[1];
                p1[2 * nt]     = (s0     > tb) ? NEG_ : c[2];
                p1[2 * nt + 1] = (s0 + 1 > tb) ? NEG_ : c[3];
            }
        }

        // softmax in registers
        softmax_reg16(p0);
        softmax_reg16(p1);

        // AV: shfl-transpose C-layout -> A-fragments, accumulate O
        float o[4] = {0.f, 0.f, 0.f, 0.f};
        #pragma unroll
        for (int kk = 0; kk < 8; kk++) {
            float x0 = __shfl_sync(0xffffffffu, p0[2 * kk],     srcA);
            float y0 = __shfl_sync(0xffffffffu, p0[2 * kk + 1], srcA);
            float x1 = __shfl_sync(0xffffffffu, p0[2 * kk],     srcB);
            float y1 = __shfl_sync(0xffffffffu, p0[2 * kk + 1], srcB);
            float u0 = __shfl_sync(0xffffffffu, p1[2 * kk],     srcA);
            float w0 = __shfl_sync(0xffffffffu, p1[2 * kk + 1], srcA);
            float u1 = __shfl_sync(0xffffffffu, p1[2 * kk],     srcB);
            float w1 = __shfl_sync(0xffffffffu, p1[2 * kk + 1], srcB);
            float a0f = (tq & 1) ? y0 : x0;    // P[row g][k0+tq]
            float a2f = (tq & 1) ? y1 : x1;    // P[row g][k0+tq+4]
            float a1f = (tq & 1) ? w0 : u0;    // P[row g+8][k0+tq]
            float a3f = (tq & 1) ? w1 : u1;    // P[row g+8][k0+tq+4]

            uint32_t ah[4], al[4], bh[2], bl[2];
            tf32_split(a0f, ah[0], al[0]);
            tf32_split(a1f, ah[1], al[1]);
            tf32_split(a2f, ah[2], al[2]);
            tf32_split(a3f, ah[3], al[3]);
            const int k0 = kk * 8;
            tf32_split(Vf[(k0 + tq)     * QKV_STR + hc + g], bh[0], bl[0]);
            tf32_split(Vf[(k0 + tq + 4) * QKV_STR + hc + g], bh[1], bl[1]);
            mma8(o, ah, bh);
            mma8(o, ah, bl);
            mma8(o, al, bh);
        }
        *(float2*)&H[(r0m + g)     * H_STR + hc + 2 * tq] = make_float2(o[0], o[1]);
        *(float2*)&H[(r0m + g + 8) * H_STR + hc + 2 * tq] = make_float2(o[2], o[3]);
    }
    __syncthreads();   // O complete before FFN1

    // ---- FFN layer 1: U = relu(O @ W1 + b1) -> Qf ----
    {
        float acc[4][4];
        #pragma unroll
        for (int i = 0; i < 4; i++)
            #pragma unroll
            for (int j = 0; j < 4; j++) acc[i][j] = 0.0f;

        mma_gemm64<8, H_STR>(H, W1, acc, mtile, nhalf, g, tq);

        __syncthreads();   // Qf (as q) reads done; O reads done
        #pragma unroll
        for (int nt = 0; nt < 4; nt++) {
            int j0 = nhalf * 32 + nt * 8 + 2 * tq;
            float bj0 = b1[j0], bj1 = b1[j0 + 1];
            int r0 = mtile * 16 + g;
            Qf[r0 * QKV_STR + j0]           = fmaxf(acc[nt][0] + bj0, 0.0f);
            Qf[r0 * QKV_STR + j0 + 1]       = fmaxf(acc[nt][1] + bj1, 0.0f);
            Qf[(r0 + 8) * QKV_STR + j0]     = fmaxf(acc[nt][2] + bj0, 0.0f);
            Qf[(r0 + 8) * QKV_STR + j0 + 1] = fmaxf(acc[nt][3] + bj1, 0.0f);
        }
    }
    __syncthreads();

    // ---- FFN layer 2: out = U @ W2 + b2 -> global ----
    {
        float acc[4][4];
        #pragma unroll
        for (int i = 0; i < 4; i++)
            #pragma unroll
            for (int j = 0; j < 4; j++) acc[i][j] = 0.0f;

        mma_gemm64<8, QKV_STR>(Qf, W2, acc, mtile, nhalf, g, tq);

        #pragma unroll
        for (int nt = 0; nt < 4; nt++) {
            int j0 = nhalf * 32 + nt * 8 + 2 * tq;
            float bj0 = b2[j0], bj1 = b2[j0 + 1];
            int r0 = mtile * 16 + g;
            float* o0 = out + (((size_t)b * T_ + r0)     * N_ + n) * D_ + j0;
            float* o1 = out + (((size_t)b * T_ + r0 + 8) * N_ + n) * D_ + j0;
            o0[0] = acc[nt][0] + bj0;
            o0[1] = acc[nt][1] + bj1;
            o1[0] = acc[nt][2] + bj0;
            o1[1] = acc[nt][3] + bj1;
        }
    }
}

extern "C" void kernel_launch(void* const* d_in, const int* in_sizes, int n_in,
                              void* d_out, int out_size)
{
    (void)in_sizes; (void)n_in; (void)out_size;
    const float* x   = (const float*)d_in[0];
    const float* ste = (const float*)d_in[1];
    const float* Wq  = (const float*)d_in[2];
    const float* bq  = (const float*)d_in[3];
    const float* Wk  = (const float*)d_in[4];
    const float* bk  = (const float*)d_in[5];
    const float* Wv  = (const float*)d_in[6];
    const float* bv  = (const float*)d_in[7];
    const float* W1  = (const float*)d_in[8];
    const float* b1  = (const float*)d_in[9];
    const float* W2  = (const float*)d_in[10];
    const float* b2  = (const float*)d_in[11];
    float* out = (float*)d_out;

    const int smem_bytes = SMEM_FLOATS * sizeof(float);   // 86016
    static bool attr_set = false;
    if (!attr_set) {
        cudaFuncSetAttribute(temporal_attn_kernel,
                             cudaFuncAttributeMaxDynamicSharedMemorySize,
                             smem_bytes);
        attr_set = true;
    }
    temporal_attn_kernel<<<B_ * N_, 256, smem_bytes>>>(
        x, ste, Wq, bq, Wk, bk, Wv, bv, W1, b1, W2, b2, out);
}

// round 14
// speedup vs baseline: 2.0733x; 1.1075x over previous
#include <cuda_runtime.h>
#include <cstdint>

// Problem constants
#define B_ 8
#define T_ 64
#define N_ 512
#define D_ 64
#define KH_ 8
#define NEG_ (-32767.0f)

// smem (floats), one problem per CTA:
//   H  : 64 x 132 (concat(x,ste); cols 0..63 reused as attn out O)
//   Qf : 64 x 68  (q pre-scaled by 1/sqrt(d); reused as FFN hidden U)
//   Kf : 64 x 68
//   Vf : 64 x 68
#define H_STR   132
#define QKV_STR 68
#define SMEM_FLOATS (64 * H_STR + 3 * 64 * QKV_STR)   // 21504 floats = 86016 B

// ---- tf32 helpers: mask-based split (no cvt) ----
__device__ __forceinline__ void tf32_split(float v, uint32_t& hi, uint32_t& lo) {
    hi = __float_as_uint(v) & 0xffffe000u;
    lo = __float_as_uint(v - __uint_as_float(hi));
}
__device__ __forceinline__ void mma8(float c[4], const uint32_t a[4], const uint32_t b[2]) {
    asm volatile(
        "mma.sync.aligned.m16n8k8.row.col.f32.tf32.tf32.f32 "
        "{%0,%1,%2,%3}, {%4,%5,%6,%7}, {%8,%9}, {%0,%1,%2,%3};"
        : "+f"(c[0]), "+f"(c[1]), "+f"(c[2]), "+f"(c[3])
        : "r"(a[0]), "r"(a[1]), "r"(a[2]), "r"(a[3]), "r"(b[0]), "r"(b[1]));
}

// 32x16-tile GEMM accumulate: warp covers rows mrow*32..+32, cols ncol*16..+16.
// acc[mi][nt][4]: mi = 16-row half, nt = 8-col tile.
// A: smem fp32 (stride ASTR), W: global fp32 [k][64] row-major. 3-term tf32 split.
// B-load count halved vs 16x32 tiling (LDG wavefronts are the expensive resource);
// A-side LDS doubled (conflict-free, cheap).
template<int KSTEPS, int ASTR>
__device__ __forceinline__ void mma_gemm64(const float* __restrict__ A,
                                           const float* __restrict__ W,
                                           float acc[2][2][4],
                                           int mrow, int ncol, int g, int tq)
{
    const float* Ab = A + mrow * 32 * ASTR;
    #pragma unroll
    for (int kk = 0; kk < KSTEPS; kk++) {
        const int k0 = kk * 8;
        uint32_t ah[2][4], al[2][4];
        #pragma unroll
        for (int mi = 0; mi < 2; mi++) {
            const float* Am = Ab + mi * 16 * ASTR;
            tf32_split(Am[g * ASTR + k0 + tq],           ah[mi][0], al[mi][0]);
            tf32_split(Am[(g + 8) * ASTR + k0 + tq],     ah[mi][1], al[mi][1]);
            tf32_split(Am[g * ASTR + k0 + tq + 4],       ah[mi][2], al[mi][2]);
            tf32_split(Am[(g + 8) * ASTR + k0 + tq + 4], ah[mi][3], al[mi][3]);
        }
        float bv0[2], bv1[2];
        #pragma unroll
        for (int nt = 0; nt < 2; nt++) {
            const float* Wb = W + k0 * 64 + ncol * 16 + nt * 8;
            bv0[nt] = Wb[tq * 64 + g];
            bv1[nt] = Wb[(tq + 4) * 64 + g];
        }
        #pragma unroll
        for (int nt = 0; nt < 2; nt++) {
            uint32_t bh[2], bl[2];
            tf32_split(bv0[nt], bh[0], bl[0]);
            tf32_split(bv1[nt], bh[1], bl[1]);
            #pragma unroll
            for (int mi = 0; mi < 2; mi++) {
                mma8(acc[mi][nt], ah[mi], bh);
                mma8(acc[mi][nt], ah[mi], bl);
                mma8(acc[mi][nt], al[mi], bh);
            }
        }
    }
}

// register softmax over one 64-wide row held as 16 values/lane across 4 tq-lanes
__device__ __forceinline__ void softmax_reg16(float* __restrict__ v) {
    float mx = v[0];
    #pragma unroll
    for (int k = 1; k < 16; k++) mx = fmaxf(mx, v[k]);
    mx = fmaxf(mx, __shfl_xor_sync(0xffffffffu, mx, 1));
    mx = fmaxf(mx, __shfl_xor_sync(0xffffffffu, mx, 2));
    float sum = 0.0f;
    #pragma unroll
    for (int k = 0; k < 16; k++) { v[k] = __expf(v[k] - mx); sum += v[k]; }
    sum += __shfl_xor_sync(0xffffffffu, sum, 1);
    sum += __shfl_xor_sync(0xffffffffu, sum, 2);
    float inv = 1.0f / sum;
    #pragma unroll
    for (int k = 0; k < 16; k++) v[k] *= inv;
}

__global__ __launch_bounds__(256, 2)
void temporal_attn_kernel(
    const float* __restrict__ x,  const float* __restrict__ ste,
    const float* __restrict__ Wq, const float* __restrict__ bq,
    const float* __restrict__ Wk, const float* __restrict__ bk,
    const float* __restrict__ Wv, const float* __restrict__ bv,
    const float* __restrict__ W1, const float* __restrict__ b1,
    const float* __restrict__ W2, const float* __restrict__ b2,
    float* __restrict__ out)
{
    extern __shared__ float sm[];
    const int tid = threadIdx.x;      // 0..255, one problem per CTA

    const int p = blockIdx.x;
    const int n = p & (N_ - 1);
    const int b = p >> 9;

    float* H  = sm;
    float* Qf = H  + 64 * H_STR;
    float* Kf = Qf + 64 * QKV_STR;
    float* Vf = Kf + 64 * QKV_STR;

    // ---- load H = concat(x, ste): 64 x 128, float4 ----
    {
        const float* xb = x   + ((size_t)((size_t)b * T_) * N_ + n) * D_;
        const float* sb = ste + ((size_t)((size_t)b * T_) * N_ + n) * D_;
        #pragma unroll
        for (int i = 0; i < 4; i++) {
            int idx = tid + i * 256;
            int t = idx >> 4, f4 = (idx & 15) << 2;
            size_t g = (size_t)t * (N_ * D_) + f4;
            *(float4*)&H[t * H_STR + f4]      = *(const float4*)&xb[g];
            *(float4*)&H[t * H_STR + 64 + f4] = *(const float4*)&sb[g];
        }
    }
    __syncthreads();

    // lane mapping
    const int lane  = tid & 31;
    const int wl    = tid >> 5;       // warp 0..7
    const int g     = lane >> 2;
    const int tq    = lane & 3;
    // GEMM tile mapping: 2 row-blocks x 4 col-blocks
    const int mrow  = wl & 1;
    const int ncol  = wl >> 1;
    // attention mapping (independent): 4 m-tiles x 2 head-select
    const int mtile = wl & 3;
    const int hsel  = wl >> 2;

    const float rsc = 0.3535533905932738f;   // 1/sqrt(8)

    // ---- QKV projections (3 passes): relu(H[64x128] @ W[128x64] + b) ----
    // Q is pre-scaled by rsc at the epilogue.
    #pragma unroll 1
    for (int m = 0; m < 3; m++) {
        const float* W    = (m == 0) ? Wq : (m == 1) ? Wk : Wv;
        const float* bias = (m == 0) ? bq : (m == 1) ? bk : bv;
        float* dst        = (m == 0) ? Qf : (m == 1) ? Kf : Vf;
        const float sc    = (m == 0) ? rsc : 1.0f;

        float acc[2][2][4];
        #pragma unroll
        for (int i = 0; i < 2; i++)
            #pragma unroll
            for (int j = 0; j < 2; j++)
                #pragma unroll
                for (int c = 0; c < 4; c++) acc[i][j][c] = 0.0f;

        mma_gemm64<16, H_STR>(H, W, acc, mrow, ncol, g, tq);

        #pragma unroll
        for (int mi = 0; mi < 2; mi++) {
            #pragma unroll
            for (int nt = 0; nt < 2; nt++) {
                int j0 = ncol * 16 + nt * 8 + 2 * tq;
                float bj0 = bias[j0], bj1 = bias[j0 + 1];
                int r0 = mrow * 32 + mi * 16 + g;
                dst[r0 * QKV_STR + j0]           = fmaxf(acc[mi][nt][0] + bj0, 0.0f) * sc;
                dst[r0 * QKV_STR + j0 + 1]       = fmaxf(acc[mi][nt][1] + bj1, 0.0f) * sc;
                dst[(r0 + 8) * QKV_STR + j0]     = fmaxf(acc[mi][nt][2] + bj0, 0.0f) * sc;
                dst[(r0 + 8) * QKV_STR + j0 + 1] = fmaxf(acc[mi][nt][3] + bj1, 0.0f) * sc;
            }
        }
    }
    __syncthreads();   // Q,K,V visible; attention is barrier-free from here

    // ---- attention: fully register-resident per warp ----
    const int r0m  = mtile * 16;
    const int base4 = lane & ~3;            // g*4
    const int srcA  = base4 + (tq >> 1);    // shfl source for col k0+tq
    const int srcB  = srcA + 2;             // shfl source for col k0+tq+4

    #pragma unroll 1
    for (int hp = 0; hp < 4; hp++) {
        const int head = hp * 2 + hsel;
        const int hc   = head * 8;

        float p0[16], p1[16];   // rows ta=r0m+g and tb=ta+8, cols {n0+2tq, n0+2tq+1} per 8-group

        // scores: C-fragments, causal mask applied in registers
        {
            uint32_t ah[4], al[4];
            tf32_split(Qf[(r0m + g)     * QKV_STR + hc + tq],     ah[0], al[0]);
            tf32_split(Qf[(r0m + g + 8) * QKV_STR + hc + tq],     ah[1], al[1]);
            tf32_split(Qf[(r0m + g)     * QKV_STR + hc + tq + 4], ah[2], al[2]);
            tf32_split(Qf[(r0m + g + 8) * QKV_STR + hc + tq + 4], ah[3], al[3]);
            const int ta = r0m + g, tb = ta + 8;
            #pragma unroll
            for (int nt = 0; nt < 8; nt++) {
                const int n0 = nt * 8;
                uint32_t bh[2], bl[2];
                tf32_split(Kf[(n0 + g) * QKV_STR + hc + tq],     bh[0], bl[0]);
                tf32_split(Kf[(n0 + g) * QKV_STR + hc + tq + 4], bh[1], bl[1]);
                float c[4] = {0.f, 0.f, 0.f, 0.f};
                mma8(c, ah, bh);
                mma8(c, ah, bl);
                mma8(c, al, bh);
                const int s0 = n0 + 2 * tq;
                p0[2 * nt]     = (s0     > ta) ? NEG_ : c[0];
                p0[2 * nt + 1] = (s0 + 1 > ta) ? NEG_ : c[1];
                p1[2 * nt]     = (s0     > tb) ? NEG_ : c[2];
                p1[2 * nt + 1] = (s0 + 1 > tb) ? NEG_ : c[3];
            }
        }

        // softmax in registers
        softmax_reg16(p0);
        softmax_reg16(p1);

        // AV: shfl-transpose C-layout -> A-fragments, accumulate O
        float o[4] = {0.f, 0.f, 0.f, 0.f};
        #pragma unroll
        for (int kk = 0; kk < 8; kk++) {
            float x0 = __shfl_sync(0xffffffffu, p0[2 * kk],     srcA);
            float y0 = __shfl_sync(0xffffffffu, p0[2 * kk + 1], srcA);
            float x1 = __shfl_sync(0xffffffffu, p0[2 * kk],     srcB);
            float y1 = __shfl_sync(0xffffffffu, p0[2 * kk + 1], srcB);
            float u0 = __shfl_sync(0xffffffffu, p1[2 * kk],     srcA);
            float w0 = __shfl_sync(0xffffffffu, p1[2 * kk + 1], srcA);
            float u1 = __shfl_sync(0xffffffffu, p1[2 * kk],     srcB);
            float w1 = __shfl_sync(0xffffffffu, p1[2 * kk + 1], srcB);
            float a0f = (tq & 1) ? y0 : x0;    // P[row g][k0+tq]
            float a2f = (tq & 1) ? y1 : x1;    // P[row g][k0+tq+4]
            float a1f = (tq & 1) ? w0 : u0;    // P[row g+8][k0+tq]
            float a3f = (tq & 1) ? w1 : u1;    // P[row g+8][k0+tq+4]

            uint32_t ah[4], al[4], bh[2], bl[2];
            tf32_split(a0f, ah[0], al[0]);
            tf32_split(a1f, ah[1], al[1]);
            tf32_split(a2f, ah[2], al[2]);
            tf32_split(a3f, ah[3], al[3]);
            const int k0 = kk * 8;
            tf32_split(Vf[(k0 + tq)     * QKV_STR + hc + g], bh[0], bl[0]);
            tf32_split(Vf[(k0 + tq + 4) * QKV_STR + hc + g], bh[1], bl[1]);
            mma8(o, ah, bh);
            mma8(o, ah, bl);
            mma8(o, al, bh);
        }
        *(float2*)&H[(r0m + g)     * H_STR + hc + 2 * tq] = make_float2(o[0], o[1]);
        *(float2*)&H[(r0m + g + 8) * H_STR + hc + 2 * tq] = make_float2(o[2], o[3]);
    }
    __syncthreads();   // O complete before FFN1

    // ---- FFN layer 1: U = relu(O @ W1 + b1) -> Qf ----
    {
        float acc[2][2][4];
        #pragma unroll
        for (int i = 0; i < 2; i++)
            #pragma unroll
            for (int j = 0; j < 2; j++)
                #pragma unroll
                for (int c = 0; c < 4; c++) acc[i][j][c] = 0.0f;

        mma_gemm64<8, H_STR>(H, W1, acc, mrow, ncol, g, tq);

        __syncthreads();   // Qf (as q) reads done; O reads done
        #pragma unroll
        for (int mi = 0; mi < 2; mi++) {
            #pragma unroll
            for (int nt = 0; nt < 2; nt++) {
                int j0 = ncol * 16 + nt * 8 + 2 * tq;
                float bj0 = b1[j0], bj1 = b1[j0 + 1];
                int r0 = mrow * 32 + mi * 16 + g;
                Qf[r0 * QKV_STR + j0]           = fmaxf(acc[mi][nt][0] + bj0, 0.0f);
                Qf[r0 * QKV_STR + j0 + 1]       = fmaxf(acc[mi][nt][1] + bj1, 0.0f);
                Qf[(r0 + 8) * QKV_STR + j0]     = fmaxf(acc[mi][nt][2] + bj0, 0.0f);
                Qf[(r0 + 8) * QKV_STR + j0 + 1] = fmaxf(acc[mi][nt][3] + bj1, 0.0f);
            }
        }
    }
    __syncthreads();

    // ---- FFN layer 2: out = U @ W2 + b2 -> global ----
    {
        float acc[2][2][4];
        #pragma unroll
        for (int i = 0; i < 2; i++)
            #pragma unroll
            for (int j = 0; j < 2; j++)
                #pragma unroll
                for (int c = 0; c < 4; c++) acc[i][j][c] = 0.0f;

        mma_gemm64<8, QKV_STR>(Qf, W2, acc, mrow, ncol, g, tq);

        #pragma unroll
        for (int mi = 0; mi < 2; mi++) {
            #pragma unroll
            for (int nt = 0; nt < 2; nt++) {
                int j0 = ncol * 16 + nt * 8 + 2 * tq;
                float bj0 = b2[j0], bj1 = b2[j0 + 1];
                int r0 = mrow * 32 + mi * 16 + g;
                float* o0 = out + (((size_t)b * T_ + r0)     * N_ + n) * D_ + j0;
                float* o1 = out + (((size_t)b * T_ + r0 + 8) * N_ + n) * D_ + j0;
                o0[0] = acc[mi][nt][0] + bj0;
                o0[1] = acc[mi][nt][1] + bj1;
                o1[0] = acc[mi][nt][2] + bj0;
                o1[1] = acc[mi][nt][3] + bj1;
            }
        }
    }
}

extern "C" void kernel_launch(void* const* d_in, const int* in_sizes, int n_in,
                              void* d_out, int out_size)
{
    (void)in_sizes; (void)n_in; (void)out_size;
    const float* x   = (const float*)d_in[0];
    const float* ste = (const float*)d_in[1];
    const float* Wq  = (const float*)d_in[2];
    const float* bq  = (const float*)d_in[3];
    const float* Wk  = (const float*)d_in[4];
    const float* bk  = (const float*)d_in[5];
    const float* Wv  = (const float*)d_in[6];
    const float* bv  = (const float*)d_in[7];
    const float* W1  = (const float*)d_in[8];
    const float* b1  = (const float*)d_in[9];
    const float* W2  = (const float*)d_in[10];
    const float* b2  = (const float*)d_in[11];
    float* out = (float*)d_out;

    const int smem_bytes = SMEM_FLOATS * sizeof(float);   // 86016
    static bool attr_set = false;
    if (!attr_set) {
        cudaFuncSetAttribute(temporal_attn_kernel,
                             cudaFuncAttributeMaxDynamicSharedMemorySize,
                             smem_bytes);
        attr_set = true;
    }
    temporal_attn_kernel<<<B_ * N_, 256, smem_bytes>>>(
        x, ste, Wq, bq, Wk, bk, Wv, bv, W1, b1, W2, b2, out);
}